// round 14
// baseline (speedup 1.0000x reference)
#include <cuda_runtime.h>
#include <cuda_fp16.h>
#include <math.h>

#define NMAX 100000
#define EMAX 3200000
#define D 128
#define KSTEPS 10
#define LVLS (KSTEPS + 1)
#define SCAN_B 1024
#define SCAN_NB ((NMAX + SCAN_B - 1) / SCAN_B)   // 98

// ---- scratch (allocation-free rule: static __device__ arrays) ----
// Levels 0..9 pre-scaled by src_norm, fp16: G[k] = h_k * srcn.
// Level 10 is never materialized (fused into the last spmm step).
__device__ __half2 g_G[(size_t)KSTEPS * NMAX * (D / 2)];   // 256 MB
__device__ int     g_indeg[NMAX];
__device__ int     g_outdeg[NMAX];
__device__ float   g_w[NMAX];        // dstn * srcn (spmm output scale)
__device__ float   g_srcn_inv[NMAX];
__device__ int     g_rowoff[NMAX + 1];
__device__ int     g_cursor[NMAX];   // seeded to rowoff by scan3
__device__ int     g_csr[EMAX];
__device__ int     g_bsum[SCAN_NB];
__device__ int     g_boff[SCAN_NB];

__global__ void k_zero(int n) {
    int i = blockIdx.x * blockDim.x + threadIdx.x;
    if (i < n) { g_indeg[i] = 0; g_outdeg[i] = 0; }
}

__global__ void k_count(const int* __restrict__ src, const int* __restrict__ dst, int e) {
    int i = blockIdx.x * blockDim.x + threadIdx.x;
    if (i < e) {
        atomicAdd(&g_indeg[dst[i]], 1);
        atomicAdd(&g_outdeg[src[i]], 1);
    }
}

// warp per node: computes norms (identical expressions/order to the old
// k_norm, so results are bit-identical) and G[0] = feats * src_norm (fp16).
__global__ void k_copy(const float* __restrict__ feats, int n) {
    int gw   = (blockIdx.x * blockDim.x + threadIdx.x) >> 5;
    int lane = threadIdx.x & 31;
    if (gw >= n) return;

    float dn = rsqrtf((float)max(g_indeg[gw], 1));
    float sd = sqrtf((float)max(g_outdeg[gw], 1));
    float sn = 1.f / sd;
    if (lane == 0) {
        g_srcn_inv[gw] = sd;
        g_w[gw]        = dn * sn;
    }

    float4 v = reinterpret_cast<const float4*>(feats)[(size_t)gw * (D / 4) + lane];
    __half2 p0 = __floats2half2_rn(v.x * sn, v.y * sn);
    __half2 p1 = __floats2half2_rn(v.z * sn, v.w * sn);
    uint2 ow;
    ow.x = *reinterpret_cast<unsigned int*>(&p0);
    ow.y = *reinterpret_cast<unsigned int*>(&p1);
    *reinterpret_cast<uint2*>(g_G + (size_t)gw * (D / 2) + 2 * lane) = ow;
}

// ---- multi-block coalesced scan ----
__global__ void k_scan1(int n) {
    __shared__ int wsum[32];
    int t = threadIdx.x, b = blockIdx.x;
    int i = b * SCAN_B + t;
    int lane = t & 31, wid = t >> 5;
    int x = (i < n) ? g_indeg[i] : 0;

    int v = x;
    #pragma unroll
    for (int o = 1; o < 32; o <<= 1) {
        int y = __shfl_up_sync(0xFFFFFFFFu, v, o);
        if (lane >= o) v += y;
    }
    if (lane == 31) wsum[wid] = v;
    __syncthreads();
    if (wid == 0) {
        int w = wsum[lane];
        #pragma unroll
        for (int o = 1; o < 32; o <<= 1) {
            int y = __shfl_up_sync(0xFFFFFFFFu, w, o);
            if (lane >= o) w += y;
        }
        wsum[lane] = w;
    }
    __syncthreads();

    int incl = v + (wid ? wsum[wid - 1] : 0);
    if (i < n) g_rowoff[i] = incl - x;
    if (t == SCAN_B - 1) g_bsum[b] = incl;
}

__global__ void k_scan2(int n) {
    __shared__ int sh[SCAN_NB];
    int t = threadIdx.x;
    if (t < SCAN_NB) sh[t] = g_bsum[t];
    __syncthreads();
    if (t == 0) {
        int acc = 0;
        for (int b = 0; b < SCAN_NB; b++) { int v = sh[b]; g_boff[b] = acc; acc += v; }
        g_rowoff[n] = acc;
    }
}

__global__ void k_scan3(int n) {
    int t = threadIdx.x, b = blockIdx.x;
    int i = b * SCAN_B + t;
    if (i < n) {
        int r = g_rowoff[i] + g_boff[b];
        g_rowoff[i] = r;
        g_cursor[i] = r;
    }
}

__global__ void k_fill(const int* __restrict__ src, const int* __restrict__ dst, int e) {
    int i = blockIdx.x * blockDim.x + threadIdx.x;
    if (i < e) {
        int p = atomicAdd(&g_cursor[dst[i]], 1);
        g_csr[p] = src[i];
    }
}

__device__ __forceinline__ void acc8(uint4 raw, float* a) {
    __half2 h0 = *reinterpret_cast<__half2*>(&raw.x);
    __half2 h1 = *reinterpret_cast<__half2*>(&raw.y);
    __half2 h2 = *reinterpret_cast<__half2*>(&raw.z);
    __half2 h3 = *reinterpret_cast<__half2*>(&raw.w);
    float2 f0 = __half22float2(h0);
    float2 f1 = __half22float2(h1);
    float2 f2 = __half22float2(h2);
    float2 f3 = __half22float2(h3);
    a[0] += f0.x; a[1] += f0.y; a[2] += f1.x; a[3] += f1.y;
    a[4] += f2.x; a[5] += f2.y; a[6] += f3.x; a[7] += f3.y;
}

// shared gather mainloop (R7-proven, arithmetic order unchanged)
__device__ __forceinline__ void spmm_gather(int gw, const uint4* __restrict__ Gin,
                                            int lane, int h, int half, float* a) {
    int beg = g_rowoff[gw];
    int end = g_rowoff[gw + 1];

    int i = beg;
    for (; i + 32 <= end; i += 32) {
        int idx = g_csr[i + lane];
        #pragma unroll
        for (int j = 0; j < 16; j++) {
            int u = __shfl_sync(0xFFFFFFFFu, idx, 2 * j + half);
            acc8(Gin[(size_t)u * 16 + h], a);
        }
    }
    int m = end - i;
    if (m > 0) {
        int idx = (lane < m) ? g_csr[i + lane] : 0;
        int j = 0;
        for (; j + 2 <= m; j += 2) {               // warp-uniform bound
            int u = __shfl_sync(0xFFFFFFFFu, idx, j + half);
            acc8(Gin[(size_t)u * 16 + h], a);
        }
        if (j < m) {
            int u = __shfl_sync(0xFFFFFFFFu, idx, j);
            if (half == 0) acc8(Gin[(size_t)u * 16 + h], a);
        }
    }
    #pragma unroll
    for (int d = 0; d < 8; d++) a[d] += __shfl_xor_sync(0xFFFFFFFFu, a[d], 16);
}

// pull-based SpMM for k = 1..9. T=128: ~90 regs/thread -> 5 blocks
// = 20 warps/SM. Proven best configuration.
#define SPMM_T 128
__global__ void __launch_bounds__(SPMM_T) k_spmm(int n, int k) {
    int gw   = (blockIdx.x * blockDim.x + threadIdx.x) >> 5;
    int lane = threadIdx.x & 31;
    if (gw >= n) return;
    const uint4* __restrict__ Gin =
        reinterpret_cast<const uint4*>(g_G + (size_t)(k - 1) * NMAX * (D / 2));
    int h    = lane & 15;
    int half = lane >> 4;

    float a[8];
    #pragma unroll
    for (int d = 0; d < 8; d++) a[d] = 0.f;

    spmm_gather(gw, Gin, lane, h, half, a);

    float w = g_w[gw];
    if (lane < 16) {
        __half2 o0 = __floats2half2_rn(a[0] * w, a[1] * w);
        __half2 o1 = __floats2half2_rn(a[2] * w, a[3] * w);
        __half2 o2 = __floats2half2_rn(a[4] * w, a[5] * w);
        __half2 o3 = __floats2half2_rn(a[6] * w, a[7] * w);
        uint4 ow;
        ow.x = *reinterpret_cast<unsigned int*>(&o0);
        ow.y = *reinterpret_cast<unsigned int*>(&o1);
        ow.z = *reinterpret_cast<unsigned int*>(&o2);
        ow.w = *reinterpret_cast<unsigned int*>(&o3);
        reinterpret_cast<uint4*>(g_G + ((size_t)k * NMAX + gw) * (D / 2))[h] = ow;
    }
}

// last step (k = 10) fused with the gated combination.
__global__ void __launch_bounds__(SPMM_T) k_spmm_last(int n, const float* __restrict__ s,
                                                      float* __restrict__ out) {
    int gw   = (blockIdx.x * blockDim.x + threadIdx.x) >> 5;
    int lane = threadIdx.x & 31;
    if (gw >= n) return;
    const uint4* __restrict__ Gin =
        reinterpret_cast<const uint4*>(g_G + (size_t)(KSTEPS - 1) * NMAX * (D / 2));
    int h    = lane & 15;
    int half = lane >> 4;

    float a[8];
    #pragma unroll
    for (int d = 0; d < 8; d++) a[d] = 0.f;

    spmm_gather(gw, Gin, lane, h, half, a);

    // g10 = round_fp16(h10 * srcn) — identical bits to the stored path
    float w = g_w[gw];
    __half2 q0 = __floats2half2_rn(a[0] * w, a[1] * w);
    __half2 q1 = __floats2half2_rn(a[2] * w, a[3] * w);
    __half2 q2 = __floats2half2_rn(a[4] * w, a[5] * w);
    __half2 q3 = __floats2half2_rn(a[6] * w, a[7] * w);
    float g10[8];
    { float2 f;
      f = __half22float2(q0); g10[0] = f.x; g10[1] = f.y;
      f = __half22float2(q1); g10[2] = f.x; g10[3] = f.y;
      f = __half22float2(q2); g10[4] = f.x; g10[5] = f.y;
      f = __half22float2(q3); g10[6] = f.x; g10[7] = f.y; }

    float sv[8];
    { const float4* sp = reinterpret_cast<const float4*>(s) + 2 * h;
      float4 s0 = sp[0], s1 = sp[1];
      sv[0] = s0.x; sv[1] = s0.y; sv[2] = s0.z; sv[3] = s0.w;
      sv[4] = s1.x; sv[5] = s1.y; sv[6] = s1.z; sv[7] = s1.w; }

    float inv = g_srcn_inv[gw];
    float acc[8];
    #pragma unroll
    for (int d = 0; d < 8; d++) acc[d] = 0.f;

    for (int k = 0; k < KSTEPS; k++) {
        uint4 raw = reinterpret_cast<const uint4*>(
            g_G + (size_t)k * NMAX * (D / 2))[(size_t)gw * 16 + h];
        float f[8];
        { __half2 h0 = *reinterpret_cast<__half2*>(&raw.x);
          __half2 h1 = *reinterpret_cast<__half2*>(&raw.y);
          __half2 h2 = *reinterpret_cast<__half2*>(&raw.z);
          __half2 h3 = *reinterpret_cast<__half2*>(&raw.w);
          float2 t;
          t = __half22float2(h0); f[0] = t.x; f[1] = t.y;
          t = __half22float2(h1); f[2] = t.x; f[3] = t.y;
          t = __half22float2(h2); f[4] = t.x; f[5] = t.y;
          t = __half22float2(h3); f[6] = t.x; f[7] = t.y; }

        float pd = 0.f;
        #pragma unroll
        for (int d = 0; d < 8; d++) pd = fmaf(f[d], sv[d], pd);
        #pragma unroll
        for (int o = 8; o; o >>= 1) pd += __shfl_xor_sync(0xFFFFFFFFu, pd, o);
        float sg = 1.f / (1.f + expf(-pd * inv));
        #pragma unroll
        for (int d = 0; d < 8; d++) acc[d] = fmaf(sg, f[d], acc[d]);
    }
    {
        float pd = 0.f;
        #pragma unroll
        for (int d = 0; d < 8; d++) pd = fmaf(g10[d], sv[d], pd);
        #pragma unroll
        for (int o = 8; o; o >>= 1) pd += __shfl_xor_sync(0xFFFFFFFFu, pd, o);
        float sg = 1.f / (1.f + expf(-pd * inv));
        #pragma unroll
        for (int d = 0; d < 8; d++) acc[d] = fmaf(sg, g10[d], acc[d]);
    }

    if (half == 0) {
        float4* op = reinterpret_cast<float4*>(out + (size_t)gw * D + 8 * h);
        op[0] = make_float4(acc[0] * inv, acc[1] * inv, acc[2] * inv, acc[3] * inv);
        op[1] = make_float4(acc[4] * inv, acc[5] * inv, acc[6] * inv, acc[7] * inv);
    }
}

extern "C" void kernel_launch(void* const* d_in, const int* in_sizes, int n_in,
                              void* d_out, int out_size) {
    const float* feats = (const float*)d_in[0];
    const float* s     = (const float*)d_in[1];
    const int*   src   = (const int*)d_in[2];
    const int*   dst   = (const int*)d_in[3];
    float* out = (float*)d_out;
    int n = in_sizes[0] / D;   // 100000
    int e = in_sizes[2];       // 3200000
    const int T = 256;

    k_zero <<<(n + T - 1) / T, T>>>(n);
    k_count<<<(e + T - 1) / T, T>>>(src, dst, e);

    k_copy <<<(n * 32 + T - 1) / T, T>>>(feats, n);   // norms + level 0

    k_scan1<<<SCAN_NB, SCAN_B>>>(n);
    k_scan2<<<1, 128>>>(n);
    k_scan3<<<SCAN_NB, SCAN_B>>>(n);

    k_fill <<<(e + T - 1) / T, T>>>(src, dst, e);

    int spmm_grid = (n * 32 + SPMM_T - 1) / SPMM_T;
    for (int k = 1; k < KSTEPS; k++)
        k_spmm<<<spmm_grid, SPMM_T>>>(n, k);

    k_spmm_last<<<spmm_grid, SPMM_T>>>(n, s, out);
}

// round 15
// speedup vs baseline: 1.0168x; 1.0168x over previous
#include <cuda_runtime.h>
#include <cuda_fp16.h>
#include <math.h>

#define NMAX 100000
#define EMAX 3200000
#define D 128
#define KSTEPS 10
#define LVLS (KSTEPS + 1)
#define SCAN_B 1024
#define SCAN_NB ((NMAX + SCAN_B - 1) / SCAN_B)   // 98

// ---- scratch (allocation-free rule: static __device__ arrays) ----
// Levels 0..9 pre-scaled by src_norm, fp16: G[k] = h_k * srcn.
// Level 10 is never materialized (fused into the last spmm step).
__device__ __half2 g_G[(size_t)KSTEPS * NMAX * (D / 2)];   // 256 MB
__device__ int     g_indeg[NMAX];
__device__ int     g_outdeg[NMAX];
__device__ float   g_w[NMAX];        // dstn * srcn (spmm output scale)
__device__ float   g_srcn_inv[NMAX];
__device__ int     g_rowoff[NMAX + 1];
__device__ int     g_cursor[NMAX];   // seeded to rowoff by scan3
__device__ int     g_csr[EMAX];
__device__ int     g_bsum[SCAN_NB];
__device__ int     g_boff[SCAN_NB];

__global__ void k_zero(int n) {
    int i = blockIdx.x * blockDim.x + threadIdx.x;
    if (i < n) { g_indeg[i] = 0; g_outdeg[i] = 0; }
}

__global__ void k_count(const int* __restrict__ src, const int* __restrict__ dst, int e) {
    int i = blockIdx.x * blockDim.x + threadIdx.x;
    if (i < e) {
        atomicAdd(&g_indeg[dst[i]], 1);
        atomicAdd(&g_outdeg[src[i]], 1);
    }
}

// warp per node: computes norms (identical expressions/order as always,
// bit-identical results) and G[0] = feats * src_norm (fp16).
__global__ void k_copy(const float* __restrict__ feats, int n) {
    int gw   = (blockIdx.x * blockDim.x + threadIdx.x) >> 5;
    int lane = threadIdx.x & 31;
    if (gw >= n) return;

    float dn = rsqrtf((float)max(g_indeg[gw], 1));
    float sd = sqrtf((float)max(g_outdeg[gw], 1));
    float sn = 1.f / sd;
    if (lane == 0) {
        g_srcn_inv[gw] = sd;
        g_w[gw]        = dn * sn;
    }

    float4 v = reinterpret_cast<const float4*>(feats)[(size_t)gw * (D / 4) + lane];
    __half2 p0 = __floats2half2_rn(v.x * sn, v.y * sn);
    __half2 p1 = __floats2half2_rn(v.z * sn, v.w * sn);
    uint2 ow;
    ow.x = *reinterpret_cast<unsigned int*>(&p0);
    ow.y = *reinterpret_cast<unsigned int*>(&p1);
    *reinterpret_cast<uint2*>(g_G + (size_t)gw * (D / 2) + 2 * lane) = ow;
}

// ---- multi-block coalesced scan ----
__global__ void k_scan1(int n) {
    __shared__ int wsum[32];
    int t = threadIdx.x, b = blockIdx.x;
    int i = b * SCAN_B + t;
    int lane = t & 31, wid = t >> 5;
    int x = (i < n) ? g_indeg[i] : 0;

    int v = x;
    #pragma unroll
    for (int o = 1; o < 32; o <<= 1) {
        int y = __shfl_up_sync(0xFFFFFFFFu, v, o);
        if (lane >= o) v += y;
    }
    if (lane == 31) wsum[wid] = v;
    __syncthreads();
    if (wid == 0) {
        int w = wsum[lane];
        #pragma unroll
        for (int o = 1; o < 32; o <<= 1) {
            int y = __shfl_up_sync(0xFFFFFFFFu, w, o);
            if (lane >= o) w += y;
        }
        wsum[lane] = w;
    }
    __syncthreads();

    int incl = v + (wid ? wsum[wid - 1] : 0);
    if (i < n) g_rowoff[i] = incl - x;
    if (t == SCAN_B - 1) g_bsum[b] = incl;
}

__global__ void k_scan2(int n) {
    __shared__ int sh[SCAN_NB];
    int t = threadIdx.x;
    if (t < SCAN_NB) sh[t] = g_bsum[t];
    __syncthreads();
    if (t == 0) {
        int acc = 0;
        for (int b = 0; b < SCAN_NB; b++) { int v = sh[b]; g_boff[b] = acc; acc += v; }
        g_rowoff[n] = acc;
    }
}

__global__ void k_scan3(int n) {
    int t = threadIdx.x, b = blockIdx.x;
    int i = b * SCAN_B + t;
    if (i < n) {
        int r = g_rowoff[i] + g_boff[b];
        g_rowoff[i] = r;
        g_cursor[i] = r;
    }
}

__global__ void k_fill(const int* __restrict__ src, const int* __restrict__ dst, int e) {
    int i = blockIdx.x * blockDim.x + threadIdx.x;
    if (i < e) {
        int p = atomicAdd(&g_cursor[dst[i]], 1);
        g_csr[p] = src[i];
    }
}

__device__ __forceinline__ void acc8(uint4 raw, float* a) {
    __half2 h0 = *reinterpret_cast<__half2*>(&raw.x);
    __half2 h1 = *reinterpret_cast<__half2*>(&raw.y);
    __half2 h2 = *reinterpret_cast<__half2*>(&raw.z);
    __half2 h3 = *reinterpret_cast<__half2*>(&raw.w);
    float2 f0 = __half22float2(h0);
    float2 f1 = __half22float2(h1);
    float2 f2 = __half22float2(h2);
    float2 f3 = __half22float2(h3);
    a[0] += f0.x; a[1] += f0.y; a[2] += f1.x; a[3] += f1.y;
    a[4] += f2.x; a[5] += f2.y; a[6] += f3.x; a[7] += f3.y;
}

// shared gather mainloop (R7-proven, arithmetic order unchanged)
__device__ __forceinline__ void spmm_gather(int gw, const uint4* __restrict__ Gin,
                                            int lane, int h, int half, float* a) {
    int beg = g_rowoff[gw];
    int end = g_rowoff[gw + 1];

    int i = beg;
    for (; i + 32 <= end; i += 32) {
        int idx = g_csr[i + lane];
        #pragma unroll
        for (int j = 0; j < 16; j++) {
            int u = __shfl_sync(0xFFFFFFFFu, idx, 2 * j + half);
            acc8(Gin[(size_t)u * 16 + h], a);
        }
    }
    int m = end - i;
    if (m > 0) {
        int idx = (lane < m) ? g_csr[i + lane] : 0;
        int j = 0;
        for (; j + 2 <= m; j += 2) {               // warp-uniform bound
            int u = __shfl_sync(0xFFFFFFFFu, idx, j + half);
            acc8(Gin[(size_t)u * 16 + h], a);
        }
        if (j < m) {
            int u = __shfl_sync(0xFFFFFFFFu, idx, j);
            if (half == 0) acc8(Gin[(size_t)u * 16 + h], a);
        }
    }
    #pragma unroll
    for (int d = 0; d < 8; d++) a[d] += __shfl_xor_sync(0xFFFFFFFFu, a[d], 16);
}

// pull-based SpMM for k = 1..9. T=64: ~92 regs/thread -> 11 blocks
// = 22 warps/SM (vs 20 at T=128) + finer wave-tail granularity.
#define SPMM_T 64
__global__ void __launch_bounds__(SPMM_T) k_spmm(int n, int k) {
    int gw   = (blockIdx.x * blockDim.x + threadIdx.x) >> 5;
    int lane = threadIdx.x & 31;
    if (gw >= n) return;
    const uint4* __restrict__ Gin =
        reinterpret_cast<const uint4*>(g_G + (size_t)(k - 1) * NMAX * (D / 2));
    int h    = lane & 15;
    int half = lane >> 4;

    float a[8];
    #pragma unroll
    for (int d = 0; d < 8; d++) a[d] = 0.f;

    spmm_gather(gw, Gin, lane, h, half, a);

    float w = g_w[gw];
    if (lane < 16) {
        __half2 o0 = __floats2half2_rn(a[0] * w, a[1] * w);
        __half2 o1 = __floats2half2_rn(a[2] * w, a[3] * w);
        __half2 o2 = __floats2half2_rn(a[4] * w, a[5] * w);
        __half2 o3 = __floats2half2_rn(a[6] * w, a[7] * w);
        uint4 ow;
        ow.x = *reinterpret_cast<unsigned int*>(&o0);
        ow.y = *reinterpret_cast<unsigned int*>(&o1);
        ow.z = *reinterpret_cast<unsigned int*>(&o2);
        ow.w = *reinterpret_cast<unsigned int*>(&o3);
        reinterpret_cast<uint4*>(g_G + ((size_t)k * NMAX + gw) * (D / 2))[h] = ow;
    }
}

// last step (k = 10) fused with the gated combination.
__global__ void __launch_bounds__(SPMM_T) k_spmm_last(int n, const float* __restrict__ s,
                                                      float* __restrict__ out) {
    int gw   = (blockIdx.x * blockDim.x + threadIdx.x) >> 5;
    int lane = threadIdx.x & 31;
    if (gw >= n) return;
    const uint4* __restrict__ Gin =
        reinterpret_cast<const uint4*>(g_G + (size_t)(KSTEPS - 1) * NMAX * (D / 2));
    int h    = lane & 15;
    int half = lane >> 4;

    float a[8];
    #pragma unroll
    for (int d = 0; d < 8; d++) a[d] = 0.f;

    spmm_gather(gw, Gin, lane, h, half, a);

    // g10 = round_fp16(h10 * srcn) — identical bits to the stored path
    float w = g_w[gw];
    __half2 q0 = __floats2half2_rn(a[0] * w, a[1] * w);
    __half2 q1 = __floats2half2_rn(a[2] * w, a[3] * w);
    __half2 q2 = __floats2half2_rn(a[4] * w, a[5] * w);
    __half2 q3 = __floats2half2_rn(a[6] * w, a[7] * w);
    float g10[8];
    { float2 f;
      f = __half22float2(q0); g10[0] = f.x; g10[1] = f.y;
      f = __half22float2(q1); g10[2] = f.x; g10[3] = f.y;
      f = __half22float2(q2); g10[4] = f.x; g10[5] = f.y;
      f = __half22float2(q3); g10[6] = f.x; g10[7] = f.y; }

    float sv[8];
    { const float4* sp = reinterpret_cast<const float4*>(s) + 2 * h;
      float4 s0 = sp[0], s1 = sp[1];
      sv[0] = s0.x; sv[1] = s0.y; sv[2] = s0.z; sv[3] = s0.w;
      sv[4] = s1.x; sv[5] = s1.y; sv[6] = s1.z; sv[7] = s1.w; }

    float inv = g_srcn_inv[gw];
    float acc[8];
    #pragma unroll
    for (int d = 0; d < 8; d++) acc[d] = 0.f;

    for (int k = 0; k < KSTEPS; k++) {
        uint4 raw = reinterpret_cast<const uint4*>(
            g_G + (size_t)k * NMAX * (D / 2))[(size_t)gw * 16 + h];
        float f[8];
        { __half2 h0 = *reinterpret_cast<__half2*>(&raw.x);
          __half2 h1 = *reinterpret_cast<__half2*>(&raw.y);
          __half2 h2 = *reinterpret_cast<__half2*>(&raw.z);
          __half2 h3 = *reinterpret_cast<__half2*>(&raw.w);
          float2 t;
          t = __half22float2(h0); f[0] = t.x; f[1] = t.y;
          t = __half22float2(h1); f[2] = t.x; f[3] = t.y;
          t = __half22float2(h2); f[4] = t.x; f[5] = t.y;
          t = __half22float2(h3); f[6] = t.x; f[7] = t.y; }

        float pd = 0.f;
        #pragma unroll
        for (int d = 0; d < 8; d++) pd = fmaf(f[d], sv[d], pd);
        #pragma unroll
        for (int o = 8; o; o >>= 1) pd += __shfl_xor_sync(0xFFFFFFFFu, pd, o);
        float sg = 1.f / (1.f + expf(-pd * inv));
        #pragma unroll
        for (int d = 0; d < 8; d++) acc[d] = fmaf(sg, f[d], acc[d]);
    }
    {
        float pd = 0.f;
        #pragma unroll
        for (int d = 0; d < 8; d++) pd = fmaf(g10[d], sv[d], pd);
        #pragma unroll
        for (int o = 8; o; o >>= 1) pd += __shfl_xor_sync(0xFFFFFFFFu, pd, o);
        float sg = 1.f / (1.f + expf(-pd * inv));
        #pragma unroll
        for (int d = 0; d < 8; d++) acc[d] = fmaf(sg, g10[d], acc[d]);
    }

    if (half == 0) {
        float4* op = reinterpret_cast<float4*>(out + (size_t)gw * D + 8 * h);
        op[0] = make_float4(acc[0] * inv, acc[1] * inv, acc[2] * inv, acc[3] * inv);
        op[1] = make_float4(acc[4] * inv, acc[5] * inv, acc[6] * inv, acc[7] * inv);
    }
}

extern "C" void kernel_launch(void* const* d_in, const int* in_sizes, int n_in,
                              void* d_out, int out_size) {
    const float* feats = (const float*)d_in[0];
    const float* s     = (const float*)d_in[1];
    const int*   src   = (const int*)d_in[2];
    const int*   dst   = (const int*)d_in[3];
    float* out = (float*)d_out;
    int n = in_sizes[0] / D;   // 100000
    int e = in_sizes[2];       // 3200000
    const int T = 256;

    k_zero <<<(n + T - 1) / T, T>>>(n);
    k_count<<<(e + T - 1) / T, T>>>(src, dst, e);

    k_copy <<<(n * 32 + T - 1) / T, T>>>(feats, n);   // norms + level 0

    k_scan1<<<SCAN_NB, SCAN_B>>>(n);
    k_scan2<<<1, 128>>>(n);
    k_scan3<<<SCAN_NB, SCAN_B>>>(n);

    k_fill <<<(e + T - 1) / T, T>>>(src, dst, e);

    int spmm_grid = (n * 32 + SPMM_T - 1) / SPMM_T;
    for (int k = 1; k < KSTEPS; k++)
        k_spmm<<<spmm_grid, SPMM_T>>>(n, k);

    k_spmm_last<<<spmm_grid, SPMM_T>>>(n, s, out);
}

// round 16
// speedup vs baseline: 1.0257x; 1.0088x over previous
#include <cuda_runtime.h>
#include <cuda_fp16.h>
#include <math.h>

#define NMAX 100000
#define EMAX 3200000
#define D 128
#define KSTEPS 10
#define LVLS (KSTEPS + 1)
#define SCAN_B 1024
#define SCAN_NB ((NMAX + SCAN_B - 1) / SCAN_B)   // 98

// ---- scratch (allocation-free rule: static __device__ arrays) ----
// Levels 0..9 pre-scaled by src_norm, fp16: G[k] = h_k * srcn.
// Level 10 is never materialized (fused into the last spmm step).
__device__ __half2 g_G[(size_t)KSTEPS * NMAX * (D / 2)];   // 256 MB
__device__ int     g_indeg[NMAX];
__device__ int     g_outdeg[NMAX];
__device__ float   g_w[NMAX];        // dstn * srcn (spmm output scale)
__device__ float   g_srcn_inv[NMAX];
__device__ int     g_rowoff[NMAX + 1];
__device__ int     g_cursor[NMAX];   // seeded to rowoff by scan3
__device__ int     g_csr[EMAX];
__device__ int     g_bsum[SCAN_NB];
__device__ int     g_boff[SCAN_NB];

__global__ void k_zero(int n) {
    int i = blockIdx.x * blockDim.x + threadIdx.x;
    if (i < n) { g_indeg[i] = 0; g_outdeg[i] = 0; }
}

__global__ void k_count(const int* __restrict__ src, const int* __restrict__ dst, int e) {
    int i = blockIdx.x * blockDim.x + threadIdx.x;
    if (i < e) {
        atomicAdd(&g_indeg[dst[i]], 1);
        atomicAdd(&g_outdeg[src[i]], 1);
    }
}

// warp per node: computes norms (identical expressions/order as always,
// bit-identical results) and G[0] = feats * src_norm (fp16).
__global__ void k_copy(const float* __restrict__ feats, int n) {
    int gw   = (blockIdx.x * blockDim.x + threadIdx.x) >> 5;
    int lane = threadIdx.x & 31;
    if (gw >= n) return;

    float dn = rsqrtf((float)max(g_indeg[gw], 1));
    float sd = sqrtf((float)max(g_outdeg[gw], 1));
    float sn = 1.f / sd;
    if (lane == 0) {
        g_srcn_inv[gw] = sd;
        g_w[gw]        = dn * sn;
    }

    float4 v = reinterpret_cast<const float4*>(feats)[(size_t)gw * (D / 4) + lane];
    __half2 p0 = __floats2half2_rn(v.x * sn, v.y * sn);
    __half2 p1 = __floats2half2_rn(v.z * sn, v.w * sn);
    uint2 ow;
    ow.x = *reinterpret_cast<unsigned int*>(&p0);
    ow.y = *reinterpret_cast<unsigned int*>(&p1);
    *reinterpret_cast<uint2*>(g_G + (size_t)gw * (D / 2) + 2 * lane) = ow;
}

// ---- multi-block coalesced scan ----
__global__ void k_scan1(int n) {
    __shared__ int wsum[32];
    int t = threadIdx.x, b = blockIdx.x;
    int i = b * SCAN_B + t;
    int lane = t & 31, wid = t >> 5;
    int x = (i < n) ? g_indeg[i] : 0;

    int v = x;
    #pragma unroll
    for (int o = 1; o < 32; o <<= 1) {
        int y = __shfl_up_sync(0xFFFFFFFFu, v, o);
        if (lane >= o) v += y;
    }
    if (lane == 31) wsum[wid] = v;
    __syncthreads();
    if (wid == 0) {
        int w = wsum[lane];
        #pragma unroll
        for (int o = 1; o < 32; o <<= 1) {
            int y = __shfl_up_sync(0xFFFFFFFFu, w, o);
            if (lane >= o) w += y;
        }
        wsum[lane] = w;
    }
    __syncthreads();

    int incl = v + (wid ? wsum[wid - 1] : 0);
    if (i < n) g_rowoff[i] = incl - x;
    if (t == SCAN_B - 1) g_bsum[b] = incl;
}

__global__ void k_scan2(int n) {
    __shared__ int sh[SCAN_NB];
    int t = threadIdx.x;
    if (t < SCAN_NB) sh[t] = g_bsum[t];
    __syncthreads();
    if (t == 0) {
        int acc = 0;
        for (int b = 0; b < SCAN_NB; b++) { int v = sh[b]; g_boff[b] = acc; acc += v; }
        g_rowoff[n] = acc;
    }
}

__global__ void k_scan3(int n) {
    int t = threadIdx.x, b = blockIdx.x;
    int i = b * SCAN_B + t;
    if (i < n) {
        int r = g_rowoff[i] + g_boff[b];
        g_rowoff[i] = r;
        g_cursor[i] = r;
    }
}

__global__ void k_fill(const int* __restrict__ src, const int* __restrict__ dst, int e) {
    int i = blockIdx.x * blockDim.x + threadIdx.x;
    if (i < e) {
        int p = atomicAdd(&g_cursor[dst[i]], 1);
        g_csr[p] = src[i];
    }
}

__device__ __forceinline__ void acc8(uint4 raw, float* a) {
    __half2 h0 = *reinterpret_cast<__half2*>(&raw.x);
    __half2 h1 = *reinterpret_cast<__half2*>(&raw.y);
    __half2 h2 = *reinterpret_cast<__half2*>(&raw.z);
    __half2 h3 = *reinterpret_cast<__half2*>(&raw.w);
    float2 f0 = __half22float2(h0);
    float2 f1 = __half22float2(h1);
    float2 f2 = __half22float2(h2);
    float2 f3 = __half22float2(h3);
    a[0] += f0.x; a[1] += f0.y; a[2] += f1.x; a[3] += f1.y;
    a[4] += f2.x; a[5] += f2.y; a[6] += f3.x; a[7] += f3.y;
}

// shared gather mainloop (R7-proven, arithmetic order unchanged)
__device__ __forceinline__ void spmm_gather(int gw, const uint4* __restrict__ Gin,
                                            int lane, int h, int half, float* a) {
    int beg = g_rowoff[gw];
    int end = g_rowoff[gw + 1];

    int i = beg;
    for (; i + 32 <= end; i += 32) {
        int idx = g_csr[i + lane];
        #pragma unroll
        for (int j = 0; j < 16; j++) {
            int u = __shfl_sync(0xFFFFFFFFu, idx, 2 * j + half);
            acc8(Gin[(size_t)u * 16 + h], a);
        }
    }
    int m = end - i;
    if (m > 0) {
        int idx = (lane < m) ? g_csr[i + lane] : 0;
        int j = 0;
        for (; j + 2 <= m; j += 2) {               // warp-uniform bound
            int u = __shfl_sync(0xFFFFFFFFu, idx, j + half);
            acc8(Gin[(size_t)u * 16 + h], a);
        }
        if (j < m) {
            int u = __shfl_sync(0xFFFFFFFFu, idx, j);
            if (half == 0) acc8(Gin[(size_t)u * 16 + h], a);
        }
    }
    #pragma unroll
    for (int d = 0; d < 8; d++) a[d] += __shfl_xor_sync(0xFFFFFFFFu, a[d], 16);
}

// pull-based SpMM for k = 1..9. T=64: ~92 regs/thread -> 11 blocks
// = 22 warps/SM. Proven best configuration.
#define SPMM_T 64
__global__ void __launch_bounds__(SPMM_T) k_spmm(int n, int k) {
    int gw   = (blockIdx.x * blockDim.x + threadIdx.x) >> 5;
    int lane = threadIdx.x & 31;
    if (gw >= n) return;
    const uint4* __restrict__ Gin =
        reinterpret_cast<const uint4*>(g_G + (size_t)(k - 1) * NMAX * (D / 2));
    int h    = lane & 15;
    int half = lane >> 4;

    float a[8];
    #pragma unroll
    for (int d = 0; d < 8; d++) a[d] = 0.f;

    spmm_gather(gw, Gin, lane, h, half, a);

    float w = g_w[gw];
    if (lane < 16) {
        __half2 o0 = __floats2half2_rn(a[0] * w, a[1] * w);
        __half2 o1 = __floats2half2_rn(a[2] * w, a[3] * w);
        __half2 o2 = __floats2half2_rn(a[4] * w, a[5] * w);
        __half2 o3 = __floats2half2_rn(a[6] * w, a[7] * w);
        uint4 ow;
        ow.x = *reinterpret_cast<unsigned int*>(&o0);
        ow.y = *reinterpret_cast<unsigned int*>(&o1);
        ow.z = *reinterpret_cast<unsigned int*>(&o2);
        ow.w = *reinterpret_cast<unsigned int*>(&o3);
        reinterpret_cast<uint4*>(g_G + ((size_t)k * NMAX + gw) * (D / 2))[h] = ow;
    }
}

// last step (k = 10) fused with the gated combination.
// Level re-reads (0..9, 256 MB streamed once, zero reuse) use __ldcs so they
// do NOT evict the L2-resident level-9 gather set the spmm mainloop needs.
__global__ void __launch_bounds__(SPMM_T) k_spmm_last(int n, const float* __restrict__ s,
                                                      float* __restrict__ out) {
    int gw   = (blockIdx.x * blockDim.x + threadIdx.x) >> 5;
    int lane = threadIdx.x & 31;
    if (gw >= n) return;
    const uint4* __restrict__ Gin =
        reinterpret_cast<const uint4*>(g_G + (size_t)(KSTEPS - 1) * NMAX * (D / 2));
    int h    = lane & 15;
    int half = lane >> 4;

    float a[8];
    #pragma unroll
    for (int d = 0; d < 8; d++) a[d] = 0.f;

    spmm_gather(gw, Gin, lane, h, half, a);

    // g10 = round_fp16(h10 * srcn) — identical bits to the stored path
    float w = g_w[gw];
    __half2 q0 = __floats2half2_rn(a[0] * w, a[1] * w);
    __half2 q1 = __floats2half2_rn(a[2] * w, a[3] * w);
    __half2 q2 = __floats2half2_rn(a[4] * w, a[5] * w);
    __half2 q3 = __floats2half2_rn(a[6] * w, a[7] * w);
    float g10[8];
    { float2 f;
      f = __half22float2(q0); g10[0] = f.x; g10[1] = f.y;
      f = __half22float2(q1); g10[2] = f.x; g10[3] = f.y;
      f = __half22float2(q2); g10[4] = f.x; g10[5] = f.y;
      f = __half22float2(q3); g10[6] = f.x; g10[7] = f.y; }

    float sv[8];
    { const float4* sp = reinterpret_cast<const float4*>(s) + 2 * h;
      float4 s0 = sp[0], s1 = sp[1];
      sv[0] = s0.x; sv[1] = s0.y; sv[2] = s0.z; sv[3] = s0.w;
      sv[4] = s1.x; sv[5] = s1.y; sv[6] = s1.z; sv[7] = s1.w; }

    float inv = g_srcn_inv[gw];
    float acc[8];
    #pragma unroll
    for (int d = 0; d < 8; d++) acc[d] = 0.f;

    for (int k = 0; k < KSTEPS; k++) {
        // streaming hint: read once, evict-first (protects the gather set)
        uint4 raw = __ldcs(reinterpret_cast<const uint4*>(
            g_G + (size_t)k * NMAX * (D / 2)) + (size_t)gw * 16 + h);
        float f[8];
        { __half2 h0 = *reinterpret_cast<__half2*>(&raw.x);
          __half2 h1 = *reinterpret_cast<__half2*>(&raw.y);
          __half2 h2 = *reinterpret_cast<__half2*>(&raw.z);
          __half2 h3 = *reinterpret_cast<__half2*>(&raw.w);
          float2 t;
          t = __half22float2(h0); f[0] = t.x; f[1] = t.y;
          t = __half22float2(h1); f[2] = t.x; f[3] = t.y;
          t = __half22float2(h2); f[4] = t.x; f[5] = t.y;
          t = __half22float2(h3); f[6] = t.x; f[7] = t.y; }

        float pd = 0.f;
        #pragma unroll
        for (int d = 0; d < 8; d++) pd = fmaf(f[d], sv[d], pd);
        #pragma unroll
        for (int o = 8; o; o >>= 1) pd += __shfl_xor_sync(0xFFFFFFFFu, pd, o);
        float sg = 1.f / (1.f + expf(-pd * inv));
        #pragma unroll
        for (int d = 0; d < 8; d++) acc[d] = fmaf(sg, f[d], acc[d]);
    }
    {
        float pd = 0.f;
        #pragma unroll
        for (int d = 0; d < 8; d++) pd = fmaf(g10[d], sv[d], pd);
        #pragma unroll
        for (int o = 8; o; o >>= 1) pd += __shfl_xor_sync(0xFFFFFFFFu, pd, o);
        float sg = 1.f / (1.f + expf(-pd * inv));
        #pragma unroll
        for (int d = 0; d < 8; d++) acc[d] = fmaf(sg, g10[d], acc[d]);
    }

    if (half == 0) {
        float4* op = reinterpret_cast<float4*>(out + (size_t)gw * D + 8 * h);
        op[0] = make_float4(acc[0] * inv, acc[1] * inv, acc[2] * inv, acc[3] * inv);
        op[1] = make_float4(acc[4] * inv, acc[5] * inv, acc[6] * inv, acc[7] * inv);
    }
}

extern "C" void kernel_launch(void* const* d_in, const int* in_sizes, int n_in,
                              void* d_out, int out_size) {
    const float* feats = (const float*)d_in[0];
    const float* s     = (const float*)d_in[1];
    const int*   src   = (const int*)d_in[2];
    const int*   dst   = (const int*)d_in[3];
    float* out = (float*)d_out;
    int n = in_sizes[0] / D;   // 100000
    int e = in_sizes[2];       // 3200000
    const int T = 256;

    k_zero <<<(n + T - 1) / T, T>>>(n);
    k_count<<<(e + T - 1) / T, T>>>(src, dst, e);

    k_copy <<<(n * 32 + T - 1) / T, T>>>(feats, n);   // norms + level 0

    k_scan1<<<SCAN_NB, SCAN_B>>>(n);
    k_scan2<<<1, 128>>>(n);
    k_scan3<<<SCAN_NB, SCAN_B>>>(n);

    k_fill <<<(e + T - 1) / T, T>>>(src, dst, e);

    int spmm_grid = (n * 32 + SPMM_T - 1) / SPMM_T;
    for (int k = 1; k < KSTEPS; k++)
        k_spmm<<<spmm_grid, SPMM_T>>>(n, k);

    k_spmm_last<<<spmm_grid, SPMM_T>>>(n, s, out);
}

// round 17
// speedup vs baseline: 1.0326x; 1.0067x over previous
#include <cuda_runtime.h>
#include <cuda_fp16.h>
#include <math.h>

#define NMAX 100000
#define EMAX 3200000
#define D 128
#define KSTEPS 10
#define LVLS (KSTEPS + 1)
#define SCAN_B 1024
#define SCAN_NB ((NMAX + SCAN_B - 1) / SCAN_B)   // 98

// ---- scratch (allocation-free rule: static __device__ arrays) ----
// Levels 0..9 pre-scaled by src_norm, fp16: G[k] = h_k * srcn.
// Level 10 is never materialized (fused into the last spmm step).
__device__ __half2 g_G[(size_t)KSTEPS * NMAX * (D / 2)];   // 256 MB
__device__ int     g_indeg[NMAX];
__device__ int     g_outdeg[NMAX];
__device__ float   g_w[NMAX];        // dstn * srcn (spmm output scale)
__device__ float   g_srcn_inv[NMAX];
__device__ int     g_rowoff[NMAX + 1];
__device__ int     g_cursor[NMAX];   // seeded to rowoff by scan3
__device__ int     g_csr[EMAX];
__device__ int     g_bsum[SCAN_NB];
__device__ int     g_boff[SCAN_NB];

__global__ void k_zero(int n) {
    int i = blockIdx.x * blockDim.x + threadIdx.x;
    if (i < n) { g_indeg[i] = 0; g_outdeg[i] = 0; }
}

__global__ void k_count(const int* __restrict__ src, const int* __restrict__ dst, int e) {
    int i = blockIdx.x * blockDim.x + threadIdx.x;
    if (i < e) {
        atomicAdd(&g_indeg[dst[i]], 1);
        atomicAdd(&g_outdeg[src[i]], 1);
    }
}

// warp per node: computes norms (identical expressions/order as always,
// bit-identical results) and G[0] = feats * src_norm (fp16).
__global__ void k_copy(const float* __restrict__ feats, int n) {
    int gw   = (blockIdx.x * blockDim.x + threadIdx.x) >> 5;
    int lane = threadIdx.x & 31;
    if (gw >= n) return;

    float dn = rsqrtf((float)max(g_indeg[gw], 1));
    float sd = sqrtf((float)max(g_outdeg[gw], 1));
    float sn = 1.f / sd;
    if (lane == 0) {
        g_srcn_inv[gw] = sd;
        g_w[gw]        = dn * sn;
    }

    float4 v = reinterpret_cast<const float4*>(feats)[(size_t)gw * (D / 4) + lane];
    __half2 p0 = __floats2half2_rn(v.x * sn, v.y * sn);
    __half2 p1 = __floats2half2_rn(v.z * sn, v.w * sn);
    uint2 ow;
    ow.x = *reinterpret_cast<unsigned int*>(&p0);
    ow.y = *reinterpret_cast<unsigned int*>(&p1);
    *reinterpret_cast<uint2*>(g_G + (size_t)gw * (D / 2) + 2 * lane) = ow;
}

// ---- multi-block coalesced scan ----
__global__ void k_scan1(int n) {
    __shared__ int wsum[32];
    int t = threadIdx.x, b = blockIdx.x;
    int i = b * SCAN_B + t;
    int lane = t & 31, wid = t >> 5;
    int x = (i < n) ? g_indeg[i] : 0;

    int v = x;
    #pragma unroll
    for (int o = 1; o < 32; o <<= 1) {
        int y = __shfl_up_sync(0xFFFFFFFFu, v, o);
        if (lane >= o) v += y;
    }
    if (lane == 31) wsum[wid] = v;
    __syncthreads();
    if (wid == 0) {
        int w = wsum[lane];
        #pragma unroll
        for (int o = 1; o < 32; o <<= 1) {
            int y = __shfl_up_sync(0xFFFFFFFFu, w, o);
            if (lane >= o) w += y;
        }
        wsum[lane] = w;
    }
    __syncthreads();

    int incl = v + (wid ? wsum[wid - 1] : 0);
    if (i < n) g_rowoff[i] = incl - x;
    if (t == SCAN_B - 1) g_bsum[b] = incl;
}

__global__ void k_scan2(int n) {
    __shared__ int sh[SCAN_NB];
    int t = threadIdx.x;
    if (t < SCAN_NB) sh[t] = g_bsum[t];
    __syncthreads();
    if (t == 0) {
        int acc = 0;
        for (int b = 0; b < SCAN_NB; b++) { int v = sh[b]; g_boff[b] = acc; acc += v; }
        g_rowoff[n] = acc;
    }
}

__global__ void k_scan3(int n) {
    int t = threadIdx.x, b = blockIdx.x;
    int i = b * SCAN_B + t;
    if (i < n) {
        int r = g_rowoff[i] + g_boff[b];
        g_rowoff[i] = r;
        g_cursor[i] = r;
    }
}

__global__ void k_fill(const int* __restrict__ src, const int* __restrict__ dst, int e) {
    int i = blockIdx.x * blockDim.x + threadIdx.x;
    if (i < e) {
        int p = atomicAdd(&g_cursor[dst[i]], 1);
        g_csr[p] = src[i];
    }
}

__device__ __forceinline__ void acc8(uint4 raw, float* a) {
    __half2 h0 = *reinterpret_cast<__half2*>(&raw.x);
    __half2 h1 = *reinterpret_cast<__half2*>(&raw.y);
    __half2 h2 = *reinterpret_cast<__half2*>(&raw.z);
    __half2 h3 = *reinterpret_cast<__half2*>(&raw.w);
    float2 f0 = __half22float2(h0);
    float2 f1 = __half22float2(h1);
    float2 f2 = __half22float2(h2);
    float2 f3 = __half22float2(h3);
    a[0] += f0.x; a[1] += f0.y; a[2] += f1.x; a[3] += f1.y;
    a[4] += f2.x; a[5] += f2.y; a[6] += f3.x; a[7] += f3.y;
}

// shared gather mainloop (R7-proven, arithmetic order unchanged).
// STREAM_CSR: in the final step csr has no future consumer -> evict-first.
template <bool STREAM_CSR>
__device__ __forceinline__ void spmm_gather(int gw, const uint4* __restrict__ Gin,
                                            int lane, int h, int half, float* a) {
    int beg = g_rowoff[gw];
    int end = g_rowoff[gw + 1];

    int i = beg;
    for (; i + 32 <= end; i += 32) {
        int idx = STREAM_CSR ? __ldcs(g_csr + i + lane) : g_csr[i + lane];
        #pragma unroll
        for (int j = 0; j < 16; j++) {
            int u = __shfl_sync(0xFFFFFFFFu, idx, 2 * j + half);
            acc8(Gin[(size_t)u * 16 + h], a);
        }
    }
    int m = end - i;
    if (m > 0) {
        int idx = (lane < m) ? (STREAM_CSR ? __ldcs(g_csr + i + lane) : g_csr[i + lane]) : 0;
        int j = 0;
        for (; j + 2 <= m; j += 2) {               // warp-uniform bound
            int u = __shfl_sync(0xFFFFFFFFu, idx, j + half);
            acc8(Gin[(size_t)u * 16 + h], a);
        }
        if (j < m) {
            int u = __shfl_sync(0xFFFFFFFFu, idx, j);
            if (half == 0) acc8(Gin[(size_t)u * 16 + h], a);
        }
    }
    #pragma unroll
    for (int d = 0; d < 8; d++) a[d] += __shfl_xor_sync(0xFFFFFFFFu, a[d], 16);
}

// pull-based SpMM for k = 1..9. T=64: ~92 regs/thread -> 11 blocks
// = 22 warps/SM. Proven best configuration.
#define SPMM_T 64
__global__ void __launch_bounds__(SPMM_T) k_spmm(int n, int k) {
    int gw   = (blockIdx.x * blockDim.x + threadIdx.x) >> 5;
    int lane = threadIdx.x & 31;
    if (gw >= n) return;
    const uint4* __restrict__ Gin =
        reinterpret_cast<const uint4*>(g_G + (size_t)(k - 1) * NMAX * (D / 2));
    int h    = lane & 15;
    int half = lane >> 4;

    float a[8];
    #pragma unroll
    for (int d = 0; d < 8; d++) a[d] = 0.f;

    spmm_gather<false>(gw, Gin, lane, h, half, a);

    float w = g_w[gw];
    if (lane < 16) {
        __half2 o0 = __floats2half2_rn(a[0] * w, a[1] * w);
        __half2 o1 = __floats2half2_rn(a[2] * w, a[3] * w);
        __half2 o2 = __floats2half2_rn(a[4] * w, a[5] * w);
        __half2 o3 = __floats2half2_rn(a[6] * w, a[7] * w);
        uint4 ow;
        ow.x = *reinterpret_cast<unsigned int*>(&o0);
        ow.y = *reinterpret_cast<unsigned int*>(&o1);
        ow.z = *reinterpret_cast<unsigned int*>(&o2);
        ow.w = *reinterpret_cast<unsigned int*>(&o3);
        reinterpret_cast<uint4*>(g_G + ((size_t)k * NMAX + gw) * (D / 2))[h] = ow;
    }
}

// last step (k = 10) fused with the gated combination.
// Zero-reuse streams use streaming policy so they never evict the
// L2-resident level-9 gather set: level re-reads (__ldcs), csr (__ldcs),
// final out stores (__stcs).
__global__ void __launch_bounds__(SPMM_T) k_spmm_last(int n, const float* __restrict__ s,
                                                      float* __restrict__ out) {
    int gw   = (blockIdx.x * blockDim.x + threadIdx.x) >> 5;
    int lane = threadIdx.x & 31;
    if (gw >= n) return;
    const uint4* __restrict__ Gin =
        reinterpret_cast<const uint4*>(g_G + (size_t)(KSTEPS - 1) * NMAX * (D / 2));
    int h    = lane & 15;
    int half = lane >> 4;

    float a[8];
    #pragma unroll
    for (int d = 0; d < 8; d++) a[d] = 0.f;

    spmm_gather<true>(gw, Gin, lane, h, half, a);

    // g10 = round_fp16(h10 * srcn) — identical bits to the stored path
    float w = g_w[gw];
    __half2 q0 = __floats2half2_rn(a[0] * w, a[1] * w);
    __half2 q1 = __floats2half2_rn(a[2] * w, a[3] * w);
    __half2 q2 = __floats2half2_rn(a[4] * w, a[5] * w);
    __half2 q3 = __floats2half2_rn(a[6] * w, a[7] * w);
    float g10[8];
    { float2 f;
      f = __half22float2(q0); g10[0] = f.x; g10[1] = f.y;
      f = __half22float2(q1); g10[2] = f.x; g10[3] = f.y;
      f = __half22float2(q2); g10[4] = f.x; g10[5] = f.y;
      f = __half22float2(q3); g10[6] = f.x; g10[7] = f.y; }

    float sv[8];
    { const float4* sp = reinterpret_cast<const float4*>(s) + 2 * h;
      float4 s0 = sp[0], s1 = sp[1];
      sv[0] = s0.x; sv[1] = s0.y; sv[2] = s0.z; sv[3] = s0.w;
      sv[4] = s1.x; sv[5] = s1.y; sv[6] = s1.z; sv[7] = s1.w; }

    float inv = g_srcn_inv[gw];
    float acc[8];
    #pragma unroll
    for (int d = 0; d < 8; d++) acc[d] = 0.f;

    for (int k = 0; k < KSTEPS; k++) {
        // streaming hint: read once, evict-first (protects the gather set)
        uint4 raw = __ldcs(reinterpret_cast<const uint4*>(
            g_G + (size_t)k * NMAX * (D / 2)) + (size_t)gw * 16 + h);
        float f[8];
        { __half2 h0 = *reinterpret_cast<__half2*>(&raw.x);
          __half2 h1 = *reinterpret_cast<__half2*>(&raw.y);
          __half2 h2 = *reinterpret_cast<__half2*>(&raw.z);
          __half2 h3 = *reinterpret_cast<__half2*>(&raw.w);
          float2 t;
          t = __half22float2(h0); f[0] = t.x; f[1] = t.y;
          t = __half22float2(h1); f[2] = t.x; f[3] = t.y;
          t = __half22float2(h2); f[4] = t.x; f[5] = t.y;
          t = __half22float2(h3); f[6] = t.x; f[7] = t.y; }

        float pd = 0.f;
        #pragma unroll
        for (int d = 0; d < 8; d++) pd = fmaf(f[d], sv[d], pd);
        #pragma unroll
        for (int o = 8; o; o >>= 1) pd += __shfl_xor_sync(0xFFFFFFFFu, pd, o);
        float sg = 1.f / (1.f + expf(-pd * inv));
        #pragma unroll
        for (int d = 0; d < 8; d++) acc[d] = fmaf(sg, f[d], acc[d]);
    }
    {
        float pd = 0.f;
        #pragma unroll
        for (int d = 0; d < 8; d++) pd = fmaf(g10[d], sv[d], pd);
        #pragma unroll
        for (int o = 8; o; o >>= 1) pd += __shfl_xor_sync(0xFFFFFFFFu, pd, o);
        float sg = 1.f / (1.f + expf(-pd * inv));
        #pragma unroll
        for (int d = 0; d < 8; d++) acc[d] = fmaf(sg, g10[d], acc[d]);
    }

    if (half == 0) {
        float4* op = reinterpret_cast<float4*>(out + (size_t)gw * D + 8 * h);
        __stcs(op,     make_float4(acc[0] * inv, acc[1] * inv, acc[2] * inv, acc[3] * inv));
        __stcs(op + 1, make_float4(acc[4] * inv, acc[5] * inv, acc[6] * inv, acc[7] * inv));
    }
}

extern "C" void kernel_launch(void* const* d_in, const int* in_sizes, int n_in,
                              void* d_out, int out_size) {
    const float* feats = (const float*)d_in[0];
    const float* s     = (const float*)d_in[1];
    const int*   src   = (const int*)d_in[2];
    const int*   dst   = (const int*)d_in[3];
    float* out = (float*)d_out;
    int n = in_sizes[0] / D;   // 100000
    int e = in_sizes[2];       // 3200000
    const int T = 256;

    k_zero <<<(n + T - 1) / T, T>>>(n);
    k_count<<<(e + T - 1) / T, T>>>(src, dst, e);

    k_copy <<<(n * 32 + T - 1) / T, T>>>(feats, n);   // norms + level 0

    k_scan1<<<SCAN_NB, SCAN_B>>>(n);
    k_scan2<<<1, 128>>>(n);
    k_scan3<<<SCAN_NB, SCAN_B>>>(n);

    k_fill <<<(e + T - 1) / T, T>>>(src, dst, e);

    int spmm_grid = (n * 32 + SPMM_T - 1) / SPMM_T;
    for (int k = 1; k < KSTEPS; k++)
        k_spmm<<<spmm_grid, SPMM_T>>>(n, k);

    k_spmm_last<<<spmm_grid, SPMM_T>>>(n, s, out);
}